// round 3
// baseline (speedup 1.0000x reference)
#include <cuda_runtime.h>
#include <cuda.h>
#include <cstdint>

// ============================================================================
// Scratch (device globals — no runtime allocation allowed)
// ============================================================================
__device__ __align__(1024) float g_T2[64 * 64 * 64];          // 1 MB
__device__ __align__(1024) float g_T3[64 * 64 * 64 * 64];     // 64 MB
__device__ __align__(1024) float g_W[4096 * 4096];            // 64 MB, row-major (O, I), tf32-RN

// ============================================================================
// PTX helpers (base compute_103 ISA only — NO tcgen05/'a' features)
// ============================================================================
__device__ __forceinline__ uint32_t elect_one_pred() {
    uint32_t pred;
    asm volatile(
        "{\n\t.reg .pred p;\n\t"
        "elect.sync _|p, 0xFFFFFFFF;\n\t"
        "selp.b32 %0, 1, 0, p;\n\t}"
        : "=r"(pred));
    return pred;
}

__device__ __forceinline__ uint32_t smem_to_u32(const void* smem_ptr) {
    uint32_t addr;
    asm("{ .reg .u64 tmp; cvta.to.shared.u64 tmp, %1; cvt.u32.u64 %0, tmp; }"
        : "=r"(addr) : "l"(smem_ptr));
    return addr;
}

#define MBARRIER_INIT(mbar, count) \
    asm volatile("mbarrier.init.shared.b64 [%0], %1;" \
        :: "r"((uint32_t)(mbar)), "r"((uint32_t)(count)) : "memory")

#define MBARRIER_ARRIVE(mbar) \
    asm volatile("mbarrier.arrive.shared.b64 _, [%0];" \
        :: "r"((uint32_t)(mbar)) : "memory")

#define MBARRIER_EXPECT_TX(mbar, tx_bytes) \
    asm volatile("mbarrier.arrive.expect_tx.shared.b64 _, [%0], %1;" \
        :: "r"((uint32_t)(mbar)), "r"((uint32_t)(tx_bytes)) : "memory")

#define MBARRIER_WAIT_PARITY(mbar, phase_parity) do { \
    uint32_t _mbar = (uint32_t)(mbar); \
    uint32_t _parity = (uint32_t)(phase_parity); \
    uint32_t _done; \
    asm volatile( \
        "{\n\t.reg .pred p;\n\t" \
        "mbarrier.try_wait.parity.acquire.cta.shared::cta.b64 p, [%1], %2;\n\t" \
        "selp.b32 %0, 1, 0, p;\n\t}" \
        : "=r"(_done) : "r"(_mbar), "r"(_parity) : "memory"); \
    if (!_done) { \
        asm volatile( \
            "{\n\t.reg .pred P1;\n\t" \
            "WAIT_LOOP_%=:\n\t" \
            "mbarrier.try_wait.parity.acquire.cta.shared::cta.b64 P1, [%0], %1, 0x989680;\n\t" \
            "@P1 bra.uni WAIT_DONE_%=;\n\t" \
            "bra.uni WAIT_LOOP_%=;\n\t" \
            "WAIT_DONE_%=:\n\t}" \
            :: "r"(_mbar), "r"(_parity) : "memory"); \
    } \
} while (0)

#define MBARRIER_WAIT_PARITY_RELAXED(mbar, phase_parity) do { \
    uint32_t _mbar = (uint32_t)(mbar); \
    uint32_t _parity = (uint32_t)(phase_parity); \
    uint32_t _done; \
    asm volatile( \
        "{\n\t.reg .pred p;\n\t" \
        "mbarrier.try_wait.parity.relaxed.cta.shared::cta.b64 p, [%1], %2, 0x989680;\n\t" \
        "selp.b32 %0, 1, 0, p;\n\t}" \
        : "=r"(_done) : "r"(_mbar), "r"(_parity) : "memory"); \
    if (!_done) { \
        asm volatile( \
            "{\n\t.reg .pred P1;\n\t" \
            "WAIT_LOOP_%=:\n\t" \
            "mbarrier.try_wait.parity.relaxed.cta.shared::cta.b64 P1, [%0], %1, 0x989680;\n\t" \
            "@P1 bra.uni WAIT_DONE_%=;\n\t" \
            "bra.uni WAIT_LOOP_%=;\n\t" \
            "WAIT_DONE_%=:\n\t}" \
            :: "r"(_mbar), "r"(_parity) : "memory"); \
    } \
} while (0)

#define TMA_LOAD_2D(smem_addr, map_ptr, cx, cy, mbar) \
    asm volatile( \
        "cp.async.bulk.tensor.2d.shared::cta.global.tile.mbarrier::complete_tx::bytes " \
        "[%0], [%1, {%2, %3}], [%4];" \
        :: "r"((uint32_t)(smem_addr)), "l"(map_ptr), \
           "r"((int32_t)(cx)), "r"((int32_t)(cy)), "r"((uint32_t)(mbar)) : "memory")

#define LDSM_X4(r0, r1, r2, r3, addr) \
    asm volatile("ldmatrix.sync.aligned.m8n8.x4.shared.b16 {%0,%1,%2,%3}, [%4];" \
        : "=r"(r0), "=r"(r1), "=r"(r2), "=r"(r3) : "r"(addr))

#define LDSM_X2(r0, r1, addr) \
    asm volatile("ldmatrix.sync.aligned.m8n8.x2.shared.b16 {%0,%1}, [%2];" \
        : "=r"(r0), "=r"(r1) : "r"(addr))

__device__ __forceinline__ void mma_tf32(float* c, const uint32_t* a, const uint32_t* b) {
    asm volatile(
        "mma.sync.aligned.m16n8k8.row.col.f32.tf32.tf32.f32 "
        "{%0,%1,%2,%3}, {%4,%5,%6,%7}, {%8,%9}, {%0,%1,%2,%3};"
        : "+f"(c[0]), "+f"(c[1]), "+f"(c[2]), "+f"(c[3])
        : "r"(a[0]), "r"(a[1]), "r"(a[2]), "r"(a[3]), "r"(b[0]), "r"(b[1]));
}

// ============================================================================
// W reconstruction from TT cores (fp32 chain, final rounded to tf32-nearest)
// ============================================================================
__global__ void build_T2(const float* __restrict__ c0, const float* __restrict__ c1) {
    int idx = blockIdx.x * 256 + threadIdx.x;          // 64*64*64
    int r2 = idx & 63, b = (idx >> 6) & 63, a = idx >> 12;
    float s = 0.f;
#pragma unroll 8
    for (int r1 = 0; r1 < 64; r1++)
        s += c0[a * 64 + r1] * c1[r1 * 4096 + b * 64 + r2];
    g_T2[idx] = s;
}

__global__ void build_T3(const float* __restrict__ c2) {
    int idx = blockIdx.x * 256 + threadIdx.x;          // 64^4
    int r3 = idx & 63, c = (idx >> 6) & 63, ab = idx >> 12;
    float s = 0.f;
#pragma unroll 8
    for (int r2 = 0; r2 < 64; r2++)
        s += g_T2[ab * 64 + r2] * c2[r2 * 4096 + c * 64 + r3];
    g_T3[idx] = s;
}

__global__ void build_W(const float* __restrict__ c3) {
    int idx = blockIdx.x * 256 + threadIdx.x;          // o*4096 + i
    int o = idx >> 12, i = idx & 4095;
    int o1 = (o >> 9) & 7, o2 = (o >> 6) & 7, o3 = (o >> 3) & 7, o4 = o & 7;
    int i1 = (i >> 9) & 7, i2 = (i >> 6) & 7, i3 = (i >> 3) & 7, i4 = i & 7;
    int a = i1 * 8 + o1, b = i2 * 8 + o2, c = i3 * 8 + o3, d = i4 * 8 + o4;
    const float* t3 = &g_T3[(((a * 64 + b) * 64 + c) * 64)];
    float s = 0.f;
#pragma unroll 8
    for (int r3 = 0; r3 < 64; r3++)
        s += t3[r3] * c3[r3 * 64 + d];
    uint32_t w32;
    asm("cvt.rna.tf32.f32 %0, %1;" : "=r"(w32) : "f"(s));   // RN to tf32
    g_W[idx] = __uint_as_float(w32);
}

// ============================================================================
// Main GEMM: out[m, o] = sum_i x[m,i] * W[o,i] + bias[o]
// CTA 128(M) x 256(N) x 32(K); 8 compute warps (warp tile 64x64) + 1 TMA warp.
// 4-stage TMA/mbarrier pipeline, SW128 swizzle, ldmatrix + mma.sync tf32.
// x is consumed raw fp32 (HMMA truncates to tf32; W is RN-rounded).
// ============================================================================
static constexpr int TILE_M = 128, TILE_N = 256, TILE_K = 32;
static constexpr int STAGES = 4;
static constexpr int NKCH = 4096 / TILE_K;            // 128
static constexpr int A_BYTES = TILE_M * TILE_K * 4;   // 16384
static constexpr int B_BYTES = TILE_N * TILE_K * 4;   // 32768
static constexpr int STAGE_BYTES = A_BYTES + B_BYTES; // 49152
static constexpr int OFF_FULL = 0;    // 4 x 8B
static constexpr int OFF_EMPTY = 64;  // 4 x 8B
static constexpr int OFF_DATA = 1024;
static constexpr int SMEM_BYTES = OFF_DATA + STAGES * STAGE_BYTES; // 197632
static constexpr int NCW = 8;         // compute warps
static constexpr int NTHREADS = (NCW + 1) * 32;  // 288

__global__ void __launch_bounds__(NTHREADS, 1) mpo_gemm(
    const __grid_constant__ CUtensorMap tmx,
    const __grid_constant__ CUtensorMap tmw,
    const float* __restrict__ bias,
    float* __restrict__ out)
{
    extern __shared__ __align__(1024) char smem[];
    const uint32_t sb = smem_to_u32(smem);
    const int tid  = threadIdx.x;
    const int wid  = tid >> 5, lane = tid & 31;
    const int nt_b = blockIdx.x;   // N tile (16) fastest -> x panel shared in L2
    const int mt_b = blockIdx.y;   // M tile (128)

    if (tid == 0) {
        for (int s = 0; s < STAGES; s++) {
            MBARRIER_INIT(sb + OFF_FULL + 8 * s, 1);     // TMA expect_tx path
            MBARRIER_INIT(sb + OFF_EMPTY + 8 * s, NCW);  // one arrive per compute warp
        }
    }
    __syncthreads();

    if (wid == NCW) {
        // ---------------- TMA producer warp ----------------
        if (elect_one_pred()) {
            int s = 0;
            for (int j = 0; j < NKCH; j++) {
                if (j >= STAGES)
                    MBARRIER_WAIT_PARITY_RELAXED(sb + OFF_EMPTY + 8 * s,
                                                 ((j / STAGES) - 1) & 1);
                MBARRIER_EXPECT_TX(sb + OFF_FULL + 8 * s, STAGE_BYTES);
                const uint32_t a_s = sb + OFF_DATA + s * STAGE_BYTES;
                TMA_LOAD_2D(a_s,           &tmx, j * TILE_K, mt_b * TILE_M,
                            sb + OFF_FULL + 8 * s);
                TMA_LOAD_2D(a_s + A_BYTES, &tmw, j * TILE_K, nt_b * TILE_N,
                            sb + OFF_FULL + 8 * s);
                if (++s == STAGES) s = 0;
            }
        }
        return;
    }

    // ---------------- compute warps (8): warp tile 64(M) x 64(N) ----------------
    const int wm = wid >> 2;        // 0..1
    const int wn = wid & 3;         // 0..3
    const int lr = lane & 7;        // row within ldmatrix 8x8 tile
    const int t8 = lane >> 3;       // ldmatrix tile index 0..3
    const uint32_t axor = (uint32_t)lr << 4;            // SW128 swizzle term

    uint32_t arow[4], brow[8];
#pragma unroll
    for (int mt = 0; mt < 4; mt++)
        arow[mt] = (uint32_t)(wm * 64 + mt * 16 + (t8 & 1) * 8 + lr) * 128u;
#pragma unroll
    for (int nt = 0; nt < 8; nt++)
        brow[nt] = (uint32_t)(wn * 64 + nt * 8 + lr) * 128u;
    const uint32_t acol = (uint32_t)(t8 >> 1) << 4;
    const uint32_t bcol = (uint32_t)(t8 & 1) << 4;

    float acc[4][8][4];
#pragma unroll
    for (int mt = 0; mt < 4; mt++)
#pragma unroll
        for (int nt = 0; nt < 8; nt++)
#pragma unroll
            for (int e = 0; e < 4; e++) acc[mt][nt][e] = 0.f;

    int s = 0, ph = 0;
    for (int i = 0; i < NKCH; i++) {
        const uint32_t As = sb + OFF_DATA + s * STAGE_BYTES;
        const uint32_t Bs = As + A_BYTES;
        MBARRIER_WAIT_PARITY(sb + OFF_FULL + 8 * s, ph);
#pragma unroll
        for (int ks = 0; ks < 4; ks++) {
            const uint32_t acolk = ((uint32_t)(ks * 32) + acol) ^ axor;
            const uint32_t bcolk = ((uint32_t)(ks * 32) + bcol) ^ axor;
            uint32_t a[4][4], b[8][2];
#pragma unroll
            for (int mt = 0; mt < 4; mt++)
                LDSM_X4(a[mt][0], a[mt][1], a[mt][2], a[mt][3],
                        As + arow[mt] + acolk);
#pragma unroll
            for (int nt = 0; nt < 8; nt++)
                LDSM_X2(b[nt][0], b[nt][1], Bs + brow[nt] + bcolk);
#pragma unroll
            for (int mt = 0; mt < 4; mt++)
#pragma unroll
                for (int nt = 0; nt < 8; nt++)
                    mma_tf32(acc[mt][nt], a[mt], b[nt]);
        }
        if (elect_one_pred()) MBARRIER_ARRIVE(sb + OFF_EMPTY + 8 * s);
        if (++s == STAGES) { s = 0; ph ^= 1; }
    }

    // ---------------- epilogue: + bias, write fp32 ----------------
    const int m0 = mt_b * TILE_M + wm * 64;
    const int n0 = nt_b * TILE_N + wn * 64;
    const int rr = lane >> 2;
    const int cc = (lane & 3) * 2;
#pragma unroll
    for (int nt = 0; nt < 8; nt++) {
        const int col = n0 + nt * 8 + cc;
        const float2 bv = *(const float2*)&bias[col];
#pragma unroll
        for (int mt = 0; mt < 4; mt++) {
            const int r0 = m0 + mt * 16 + rr;
            float2 v0, v1;
            v0.x = acc[mt][nt][0] + bv.x;  v0.y = acc[mt][nt][1] + bv.y;
            v1.x = acc[mt][nt][2] + bv.x;  v1.y = acc[mt][nt][3] + bv.y;
            *(float2*)&out[(size_t)r0 * 4096 + col]       = v0;
            *(float2*)&out[(size_t)(r0 + 8) * 4096 + col] = v1;
        }
    }
}

// ============================================================================
// Host launcher
// ============================================================================
typedef CUresult (*TmapEncodeFn)(
    CUtensorMap*, CUtensorMapDataType, cuuint32_t, void*,
    const cuuint64_t*, const cuuint64_t*, const cuuint32_t*, const cuuint32_t*,
    CUtensorMapInterleave, CUtensorMapSwizzle, CUtensorMapL2promotion,
    CUtensorMapFloatOOBfill);

extern "C" void kernel_launch(void* const* d_in, const int* in_sizes, int n_in,
                              void* d_out, int out_size) {
    const float* x    = (const float*)d_in[0];
    const float* c0   = (const float*)d_in[1];
    const float* c1   = (const float*)d_in[2];
    const float* c2   = (const float*)d_in[3];
    const float* c3   = (const float*)d_in[4];
    const float* bias = (const float*)d_in[5];
    float* out = (float*)d_out;

    const int M = in_sizes[0] / 4096;   // 16384 rows of x

    // --- W reconstruction (~4.3 GFLOP) ---
    build_T2<<<(64 * 64 * 64) / 256, 256>>>(c0, c1);
    build_T3<<<(1 << 24) / 256, 256>>>(c2);
    build_W<<<(1 << 24) / 256, 256>>>(c3);

    // --- TMA descriptors (driver API via runtime entry point; no -lcuda) ---
    TmapEncodeFn enc = nullptr;
    cudaDriverEntryPointQueryResult st;
#if CUDART_VERSION >= 12050
    cudaGetDriverEntryPointByVersion("cuTensorMapEncodeTiled", (void**)&enc,
                                     12000, cudaEnableDefault, &st);
#else
    cudaGetDriverEntryPoint("cuTensorMapEncodeTiled", (void**)&enc,
                            cudaEnableDefault, &st);
#endif

    void* wptr = nullptr;
    cudaGetSymbolAddress(&wptr, g_W);

    CUtensorMap tmx{}, tmw{};
    {
        cuuint64_t dims[2]    = {4096ull, (cuuint64_t)M};
        cuuint64_t strides[1] = {4096ull * 4ull};
        cuuint32_t box[2]     = {TILE_K, TILE_M};   // 32 floats (=128B) x 128 rows
        cuuint32_t es[2]      = {1, 1};
        enc(&tmx, CU_TENSOR_MAP_DATA_TYPE_FLOAT32, 2, (void*)x,
            dims, strides, box, es,
            CU_TENSOR_MAP_INTERLEAVE_NONE, CU_TENSOR_MAP_SWIZZLE_128B,
            CU_TENSOR_MAP_L2_PROMOTION_L2_128B, CU_TENSOR_MAP_FLOAT_OOB_FILL_NONE);
    }
    {
        cuuint64_t dims[2]    = {4096ull, 4096ull};
        cuuint64_t strides[1] = {4096ull * 4ull};
        cuuint32_t box[2]     = {TILE_K, TILE_N};   // 32 floats x 256 rows
        cuuint32_t es[2]      = {1, 1};
        enc(&tmw, CU_TENSOR_MAP_DATA_TYPE_FLOAT32, 2, wptr,
            dims, strides, box, es,
            CU_TENSOR_MAP_INTERLEAVE_NONE, CU_TENSOR_MAP_SWIZZLE_128B,
            CU_TENSOR_MAP_L2_PROMOTION_L2_128B, CU_TENSOR_MAP_FLOAT_OOB_FILL_NONE);
    }

    cudaFuncSetAttribute(mpo_gemm, cudaFuncAttributeMaxDynamicSharedMemorySize,
                         SMEM_BYTES);
    dim3 grid(4096 / TILE_N, M / TILE_M);   // (16, 128)
    mpo_gemm<<<grid, NTHREADS, SMEM_BYTES>>>(tmx, tmw, bias, out);
}

// round 4
// speedup vs baseline: 1.5699x; 1.5699x over previous
#include <cuda_runtime.h>
#include <cuda.h>
#include <cuda_fp16.h>
#include <cstdint>

// ============================================================================
// Scratch (device globals — no runtime allocation allowed)
// ============================================================================
__device__ __align__(1024) float  g_T2[64 * 64 * 64];          // 1 MB
__device__ __align__(1024) float  g_T3[64 * 64 * 64 * 64];     // 64 MB
__device__ __align__(1024) __half g_Wh[4096 * 4096];           // 32 MB, row-major (O, I), fp16-RN
__device__ __align__(1024) __half g_Xh[16384 * 4096];          // 128 MB, x fp16-RN

// ============================================================================
// PTX helpers (base compute_103 ISA only — NO tcgen05/'a' features)
// ============================================================================
__device__ __forceinline__ uint32_t elect_one_pred() {
    uint32_t pred;
    asm volatile(
        "{\n\t.reg .pred p;\n\t"
        "elect.sync _|p, 0xFFFFFFFF;\n\t"
        "selp.b32 %0, 1, 0, p;\n\t}"
        : "=r"(pred));
    return pred;
}

__device__ __forceinline__ uint32_t smem_to_u32(const void* smem_ptr) {
    uint32_t addr;
    asm("{ .reg .u64 tmp; cvta.to.shared.u64 tmp, %1; cvt.u32.u64 %0, tmp; }"
        : "=r"(addr) : "l"(smem_ptr));
    return addr;
}

#define MBARRIER_INIT(mbar, count) \
    asm volatile("mbarrier.init.shared.b64 [%0], %1;" \
        :: "r"((uint32_t)(mbar)), "r"((uint32_t)(count)) : "memory")

#define MBARRIER_ARRIVE(mbar) \
    asm volatile("mbarrier.arrive.shared.b64 _, [%0];" \
        :: "r"((uint32_t)(mbar)) : "memory")

#define MBARRIER_EXPECT_TX(mbar, tx_bytes) \
    asm volatile("mbarrier.arrive.expect_tx.shared.b64 _, [%0], %1;" \
        :: "r"((uint32_t)(mbar)), "r"((uint32_t)(tx_bytes)) : "memory")

#define MBARRIER_WAIT_PARITY(mbar, phase_parity) do { \
    uint32_t _mbar = (uint32_t)(mbar); \
    uint32_t _parity = (uint32_t)(phase_parity); \
    uint32_t _done; \
    asm volatile( \
        "{\n\t.reg .pred p;\n\t" \
        "mbarrier.try_wait.parity.acquire.cta.shared::cta.b64 p, [%1], %2;\n\t" \
        "selp.b32 %0, 1, 0, p;\n\t}" \
        : "=r"(_done) : "r"(_mbar), "r"(_parity) : "memory"); \
    if (!_done) { \
        asm volatile( \
            "{\n\t.reg .pred P1;\n\t" \
            "WAIT_LOOP_%=:\n\t" \
            "mbarrier.try_wait.parity.acquire.cta.shared::cta.b64 P1, [%0], %1, 0x989680;\n\t" \
            "@P1 bra.uni WAIT_DONE_%=;\n\t" \
            "bra.uni WAIT_LOOP_%=;\n\t" \
            "WAIT_DONE_%=:\n\t}" \
            :: "r"(_mbar), "r"(_parity) : "memory"); \
    } \
} while (0)

#define MBARRIER_WAIT_PARITY_RELAXED(mbar, phase_parity) do { \
    uint32_t _mbar = (uint32_t)(mbar); \
    uint32_t _parity = (uint32_t)(phase_parity); \
    uint32_t _done; \
    asm volatile( \
        "{\n\t.reg .pred p;\n\t" \
        "mbarrier.try_wait.parity.relaxed.cta.shared::cta.b64 p, [%1], %2, 0x989680;\n\t" \
        "selp.b32 %0, 1, 0, p;\n\t}" \
        : "=r"(_done) : "r"(_mbar), "r"(_parity) : "memory"); \
    if (!_done) { \
        asm volatile( \
            "{\n\t.reg .pred P1;\n\t" \
            "WAIT_LOOP_%=:\n\t" \
            "mbarrier.try_wait.parity.relaxed.cta.shared::cta.b64 P1, [%0], %1, 0x989680;\n\t" \
            "@P1 bra.uni WAIT_DONE_%=;\n\t" \
            "bra.uni WAIT_LOOP_%=;\n\t" \
            "WAIT_DONE_%=:\n\t}" \
            :: "r"(_mbar), "r"(_parity) : "memory"); \
    } \
} while (0)

#define TMA_LOAD_2D(smem_addr, map_ptr, cx, cy, mbar) \
    asm volatile( \
        "cp.async.bulk.tensor.2d.shared::cta.global.tile.mbarrier::complete_tx::bytes " \
        "[%0], [%1, {%2, %3}], [%4];" \
        :: "r"((uint32_t)(smem_addr)), "l"(map_ptr), \
           "r"((int32_t)(cx)), "r"((int32_t)(cy)), "r"((uint32_t)(mbar)) : "memory")

#define LDSM_X4(r0, r1, r2, r3, addr) \
    asm volatile("ldmatrix.sync.aligned.m8n8.x4.shared.b16 {%0,%1,%2,%3}, [%4];" \
        : "=r"(r0), "=r"(r1), "=r"(r2), "=r"(r3) : "r"(addr))

__device__ __forceinline__ void mma_f16(float* c, const uint32_t* a, const uint32_t* b) {
    asm volatile(
        "mma.sync.aligned.m16n8k16.row.col.f32.f16.f16.f32 "
        "{%0,%1,%2,%3}, {%4,%5,%6,%7}, {%8,%9}, {%0,%1,%2,%3};"
        : "+f"(c[0]), "+f"(c[1]), "+f"(c[2]), "+f"(c[3])
        : "r"(a[0]), "r"(a[1]), "r"(a[2]), "r"(a[3]), "r"(b[0]), "r"(b[1]));
}

// ============================================================================
// W reconstruction from TT cores (fp32 chain, final RN-rounded to fp16)
// ============================================================================
__global__ void build_T2(const float* __restrict__ c0, const float* __restrict__ c1) {
    int idx = blockIdx.x * 256 + threadIdx.x;          // 64*64*64
    int r2 = idx & 63, b = (idx >> 6) & 63, a = idx >> 12;
    float s = 0.f;
#pragma unroll 8
    for (int r1 = 0; r1 < 64; r1++)
        s += c0[a * 64 + r1] * c1[r1 * 4096 + b * 64 + r2];
    g_T2[idx] = s;
}

__global__ void build_T3(const float* __restrict__ c2) {
    int idx = blockIdx.x * 256 + threadIdx.x;          // 64^4
    int r3 = idx & 63, c = (idx >> 6) & 63, ab = idx >> 12;
    float s = 0.f;
#pragma unroll 8
    for (int r2 = 0; r2 < 64; r2++)
        s += g_T2[ab * 64 + r2] * c2[r2 * 4096 + c * 64 + r3];
    g_T3[idx] = s;
}

__global__ void build_W(const float* __restrict__ c3) {
    int idx = blockIdx.x * 256 + threadIdx.x;          // o*4096 + i
    int o = idx >> 12, i = idx & 4095;
    int o1 = (o >> 9) & 7, o2 = (o >> 6) & 7, o3 = (o >> 3) & 7, o4 = o & 7;
    int i1 = (i >> 9) & 7, i2 = (i >> 6) & 7, i3 = (i >> 3) & 7, i4 = i & 7;
    int a = i1 * 8 + o1, b = i2 * 8 + o2, c = i3 * 8 + o3, d = i4 * 8 + o4;
    const float* t3 = &g_T3[(((a * 64 + b) * 64 + c) * 64)];
    float s = 0.f;
#pragma unroll 8
    for (int r3 = 0; r3 < 64; r3++)
        s += t3[r3] * c3[r3 * 64 + d];
    g_Wh[idx] = __float2half_rn(s);
}

// x fp32 -> fp16 (RN), 8 elements per thread
__global__ void convert_x(const float* __restrict__ x, int n8) {
    int i = blockIdx.x * 256 + threadIdx.x;
    if (i < n8) {
        const float4* src = (const float4*)x + i * 2;
        float4 v0 = src[0], v1 = src[1];
        uint4 o;
        __half2 h;
        h = __floats2half2_rn(v0.x, v0.y); o.x = *(uint32_t*)&h;
        h = __floats2half2_rn(v0.z, v0.w); o.y = *(uint32_t*)&h;
        h = __floats2half2_rn(v1.x, v1.y); o.z = *(uint32_t*)&h;
        h = __floats2half2_rn(v1.z, v1.w); o.w = *(uint32_t*)&h;
        ((uint4*)g_Xh)[i] = o;
    }
}

// ============================================================================
// Main GEMM: out[m, o] = sum_i x[m,i] * W[o,i] + bias[o]     (fp16 in, fp32 acc)
// CTA 128(M) x 256(N) x 64(K); 8 compute warps (warp tile 64x64) + 1 TMA warp.
// 4-stage TMA/mbarrier pipeline, SW128 swizzle, ldmatrix.x4 + mma m16n8k16.
// ============================================================================
static constexpr int TILE_M = 128, TILE_N = 256, TILE_K = 64;
static constexpr int STAGES = 4;
static constexpr int NKCH = 4096 / TILE_K;            // 64
static constexpr int A_BYTES = TILE_M * TILE_K * 2;   // 16384
static constexpr int B_BYTES = TILE_N * TILE_K * 2;   // 32768
static constexpr int STAGE_BYTES = A_BYTES + B_BYTES; // 49152
static constexpr int OFF_FULL = 0;    // 4 x 8B
static constexpr int OFF_EMPTY = 64;  // 4 x 8B
static constexpr int OFF_DATA = 1024;
static constexpr int SMEM_BYTES = OFF_DATA + STAGES * STAGE_BYTES; // 197632
static constexpr int NCW = 8;         // compute warps
static constexpr int NTHREADS = (NCW + 1) * 32;  // 288

__global__ void __launch_bounds__(NTHREADS, 1) mpo_gemm(
    const __grid_constant__ CUtensorMap tmx,
    const __grid_constant__ CUtensorMap tmw,
    const float* __restrict__ bias,
    float* __restrict__ out)
{
    extern __shared__ __align__(1024) char smem[];
    const uint32_t sb = smem_to_u32(smem);
    const int tid  = threadIdx.x;
    const int wid  = tid >> 5, lane = tid & 31;
    const int nt_b = blockIdx.x;   // N tile (16) fastest -> x panel shared in L2
    const int mt_b = blockIdx.y;   // M tile (128)

    if (tid == 0) {
        for (int s = 0; s < STAGES; s++) {
            MBARRIER_INIT(sb + OFF_FULL + 8 * s, 1);     // TMA expect_tx path
            MBARRIER_INIT(sb + OFF_EMPTY + 8 * s, NCW);  // one arrive per compute warp
        }
    }
    __syncthreads();

    if (wid == NCW) {
        // ---------------- TMA producer warp ----------------
        if (elect_one_pred()) {
            int s = 0;
            for (int j = 0; j < NKCH; j++) {
                if (j >= STAGES)
                    MBARRIER_WAIT_PARITY_RELAXED(sb + OFF_EMPTY + 8 * s,
                                                 ((j / STAGES) - 1) & 1);
                MBARRIER_EXPECT_TX(sb + OFF_FULL + 8 * s, STAGE_BYTES);
                const uint32_t a_s = sb + OFF_DATA + s * STAGE_BYTES;
                TMA_LOAD_2D(a_s,           &tmx, j * TILE_K, mt_b * TILE_M,
                            sb + OFF_FULL + 8 * s);
                TMA_LOAD_2D(a_s + A_BYTES, &tmw, j * TILE_K, nt_b * TILE_N,
                            sb + OFF_FULL + 8 * s);
                if (++s == STAGES) s = 0;
            }
        }
        return;
    }

    // ---------------- compute warps (8): warp tile 64(M) x 64(N) ----------------
    // SMEM rows are 128B (64 fp16). ldmatrix tile = 8 rows x 16B (8 fp16 = k8).
    const int wm = wid >> 2;        // 0..1
    const int wn = wid & 3;         // 0..3
    const int lr = lane & 7;        // row within ldmatrix 8x8 tile
    const int t8 = lane >> 3;       // ldmatrix tile index 0..3
    const uint32_t axor = (uint32_t)lr << 4;            // SW128 swizzle term

    // A fragments: m16k16 via x4 (tiles: m0-7/k0-7, m8-15/k0-7, m0-7/k8-15, m8-15/k8-15)
    uint32_t arow[4];
#pragma unroll
    for (int mt = 0; mt < 4; mt++)
        arow[mt] = (uint32_t)(wm * 64 + mt * 16 + (t8 & 1) * 8 + lr) * 128u;
    const uint32_t acol = (uint32_t)(t8 >> 1) << 4;

    // B fragments: two n8-groups per x4 (tiles: n0/k0-7, n0/k8-15, n1/k0-7, n1/k8-15)
    uint32_t brow[4];
#pragma unroll
    for (int np = 0; np < 4; np++)
        brow[np] = (uint32_t)(wn * 64 + np * 16 + ((t8 >> 1) & 1) * 8 + lr) * 128u;
    const uint32_t bcol = (uint32_t)(t8 & 1) << 4;

    float acc[4][8][4];
#pragma unroll
    for (int mt = 0; mt < 4; mt++)
#pragma unroll
        for (int nt = 0; nt < 8; nt++)
#pragma unroll
            for (int e = 0; e < 4; e++) acc[mt][nt][e] = 0.f;

    int s = 0, ph = 0;
    for (int i = 0; i < NKCH; i++) {
        const uint32_t As = sb + OFF_DATA + s * STAGE_BYTES;
        const uint32_t Bs = As + A_BYTES;
        MBARRIER_WAIT_PARITY(sb + OFF_FULL + 8 * s, ph);
#pragma unroll
        for (int ks = 0; ks < 4; ks++) {          // 4 x k16 = K64
            const uint32_t colk = (uint32_t)(ks * 32);
            const uint32_t acolk = (colk + acol) ^ axor;
            const uint32_t bcolk = (colk + bcol) ^ axor;
            uint32_t a[4][4], b[8][2];
#pragma unroll
            for (int mt = 0; mt < 4; mt++)
                LDSM_X4(a[mt][0], a[mt][1], a[mt][2], a[mt][3],
                        As + arow[mt] + acolk);
#pragma unroll
            for (int np = 0; np < 4; np++)
                LDSM_X4(b[2 * np][0], b[2 * np][1], b[2 * np + 1][0], b[2 * np + 1][1],
                        Bs + brow[np] + bcolk);
#pragma unroll
            for (int mt = 0; mt < 4; mt++)
#pragma unroll
                for (int nt = 0; nt < 8; nt++)
                    mma_f16(acc[mt][nt], a[mt], b[nt]);
        }
        if (elect_one_pred()) MBARRIER_ARRIVE(sb + OFF_EMPTY + 8 * s);
        if (++s == STAGES) { s = 0; ph ^= 1; }
    }

    // ---------------- epilogue: + bias, write fp32 ----------------
    const int m0 = mt_b * TILE_M + wm * 64;
    const int n0 = nt_b * TILE_N + wn * 64;
    const int rr = lane >> 2;
    const int cc = (lane & 3) * 2;
#pragma unroll
    for (int nt = 0; nt < 8; nt++) {
        const int col = n0 + nt * 8 + cc;
        const float2 bv = *(const float2*)&bias[col];
#pragma unroll
        for (int mt = 0; mt < 4; mt++) {
            const int r0 = m0 + mt * 16 + rr;
            float2 v0, v1;
            v0.x = acc[mt][nt][0] + bv.x;  v0.y = acc[mt][nt][1] + bv.y;
            v1.x = acc[mt][nt][2] + bv.x;  v1.y = acc[mt][nt][3] + bv.y;
            *(float2*)&out[(size_t)r0 * 4096 + col]       = v0;
            *(float2*)&out[(size_t)(r0 + 8) * 4096 + col] = v1;
        }
    }
}

// ============================================================================
// Host launcher
// ============================================================================
typedef CUresult (*TmapEncodeFn)(
    CUtensorMap*, CUtensorMapDataType, cuuint32_t, void*,
    const cuuint64_t*, const cuuint64_t*, const cuuint32_t*, const cuuint32_t*,
    CUtensorMapInterleave, CUtensorMapSwizzle, CUtensorMapL2promotion,
    CUtensorMapFloatOOBfill);

extern "C" void kernel_launch(void* const* d_in, const int* in_sizes, int n_in,
                              void* d_out, int out_size) {
    const float* x    = (const float*)d_in[0];
    const float* c0   = (const float*)d_in[1];
    const float* c1   = (const float*)d_in[2];
    const float* c2   = (const float*)d_in[3];
    const float* c3   = (const float*)d_in[4];
    const float* bias = (const float*)d_in[5];
    float* out = (float*)d_out;

    const int M = in_sizes[0] / 4096;   // 16384 rows of x

    // --- W reconstruction (~4.3 GFLOP) + x fp16 conversion ---
    build_T2<<<(64 * 64 * 64) / 256, 256>>>(c0, c1);
    build_T3<<<(1 << 24) / 256, 256>>>(c2);
    build_W<<<(1 << 24) / 256, 256>>>(c3);
    convert_x<<<(M * 4096 / 8 + 255) / 256, 256>>>(x, M * 4096 / 8);

    // --- TMA descriptors (driver API via runtime entry point; no -lcuda) ---
    TmapEncodeFn enc = nullptr;
    cudaDriverEntryPointQueryResult st;
#if CUDART_VERSION >= 12050
    cudaGetDriverEntryPointByVersion("cuTensorMapEncodeTiled", (void**)&enc,
                                     12000, cudaEnableDefault, &st);
#else
    cudaGetDriverEntryPoint("cuTensorMapEncodeTiled", (void**)&enc,
                            cudaEnableDefault, &st);
#endif

    void* wptr = nullptr;
    void* xptr = nullptr;
    cudaGetSymbolAddress(&wptr, g_Wh);
    cudaGetSymbolAddress(&xptr, g_Xh);

    CUtensorMap tmx{}, tmw{};
    {
        cuuint64_t dims[2]    = {4096ull, (cuuint64_t)M};
        cuuint64_t strides[1] = {4096ull * 2ull};
        cuuint32_t box[2]     = {TILE_K, TILE_M};   // 64 fp16 (=128B, SW128) x 128 rows
        cuuint32_t es[2]      = {1, 1};
        enc(&tmx, CU_TENSOR_MAP_DATA_TYPE_FLOAT16, 2, xptr,
            dims, strides, box, es,
            CU_TENSOR_MAP_INTERLEAVE_NONE, CU_TENSOR_MAP_SWIZZLE_128B,
            CU_TENSOR_MAP_L2_PROMOTION_L2_128B, CU_TENSOR_MAP_FLOAT_OOB_FILL_NONE);
    }
    {
        cuuint64_t dims[2]    = {4096ull, 4096ull};
        cuuint64_t strides[1] = {4096ull * 2ull};
        cuuint32_t box[2]     = {TILE_K, TILE_N};   // 64 fp16 x 256 rows
        cuuint32_t es[2]      = {1, 1};
        enc(&tmw, CU_TENSOR_MAP_DATA_TYPE_FLOAT16, 2, wptr,
            dims, strides, box, es,
            CU_TENSOR_MAP_INTERLEAVE_NONE, CU_TENSOR_MAP_SWIZZLE_128B,
            CU_TENSOR_MAP_L2_PROMOTION_L2_128B, CU_TENSOR_MAP_FLOAT_OOB_FILL_NONE);
    }

    cudaFuncSetAttribute(mpo_gemm, cudaFuncAttributeMaxDynamicSharedMemorySize,
                         SMEM_BYTES);
    dim3 grid(4096 / TILE_N, M / TILE_M);   // (16, 128)
    mpo_gemm<<<grid, NTHREADS, SMEM_BYTES>>>(tmx, tmw, bias, out);
}